// round 15
// baseline (speedup 1.0000x reference)
#include <cuda_runtime.h>
#include <cuda_bf16.h>
#include <math.h>
#include <stdint.h>

// Problem constants
#define BB 16
#define TT 2000
#define CC 1536
#define NH 8
#define DD 192
#define QQ 256
#define AA 192

// ===================== warp-MMA helpers (sm_80+ baseline) ==================
__device__ __forceinline__ uint32_t smem_u32(const void* p) {
    uint32_t a;
    asm("{ .reg .u64 t; cvta.to.shared.u64 t, %1; cvt.u32.u64 %0, t; }"
        : "=r"(a) : "l"(p));
    return a;
}
__device__ __forceinline__ void ldsm_x4(uint32_t r[4], uint32_t addr) {
    asm volatile("ldmatrix.sync.aligned.m8n8.x4.shared.b16 {%0,%1,%2,%3}, [%4];"
                 : "=r"(r[0]), "=r"(r[1]), "=r"(r[2]), "=r"(r[3]) : "r"(addr));
}
__device__ __forceinline__ void mma_bf16(float c[4], const uint32_t a[4],
                                         uint32_t b0, uint32_t b1) {
    asm volatile("mma.sync.aligned.m16n8k16.row.col.f32.bf16.bf16.f32 "
                 "{%0,%1,%2,%3}, {%4,%5,%6,%7}, {%8,%9}, {%0,%1,%2,%3};"
                 : "+f"(c[0]), "+f"(c[1]), "+f"(c[2]), "+f"(c[3])
                 : "r"(a[0]), "r"(a[1]), "r"(a[2]), "r"(a[3]), "r"(b0), "r"(b1));
}
__device__ __forceinline__ uint32_t pack_bf(float lo, float hi) {
    uint32_t r;
    asm("cvt.rn.bf16x2.f32 %0, %1, %2;" : "=r"(r) : "f"(hi), "f"(lo));
    return r;
}
__device__ __forceinline__ float bflo(uint32_t u) { return __uint_as_float(u << 16); }
__device__ __forceinline__ float bfhi(uint32_t u) { return __uint_as_float(u & 0xffff0000u); }
__device__ __forceinline__ float tanha(float x) {
    float r; asm("tanh.approx.f32 %0, %1;" : "=f"(r) : "f"(x)); return r;
}
#define CP_ASYNC16(dst, src) \
    asm volatile("cp.async.cg.shared.global [%0], [%1], 16;" :: "r"(dst), "l"(src))
#define CP_COMMIT() asm volatile("cp.async.commit_group;" ::: "memory")
#define CP_WAIT0() asm volatile("cp.async.wait_group 0;" ::: "memory")
#define CP_WAIT1() asm volatile("cp.async.wait_group 1;" ::: "memory")

// ---------------- scratch (device globals: no allocations allowed) --------
__device__ float g_c[BB * CC * 2];
__device__ float g_hck[BB * NH * QQ];
__device__ float g_t1[BB * NH * QQ];
__device__ float g_cq2[BB * NH * AA];
__device__ float g_vcqsum[NH * AA];
__device__ float g_ckdotp[BB * NH * 8];
__device__ float g_vcqdotp[BB * NH * 6];
__device__ float g_qdotp[NH * 8];
__device__ __nv_bfloat16 g_w1t[NH * QQ * DD];               // W1^T [n][q][d] bf16
__device__ __nv_bfloat16 g_qTb[NH * AA * QQ];               // query^T/sqrt(Q) bf16
__device__ float4 g_pp[BB * NH * 32 * AA];                  // pool partials per tile

// ---------------- K-front: stats + prepw + prepq + qdot (one launch) -------
__global__ __launch_bounds__(256) void k_front(
        const float* __restrict__ ht, const float* __restrict__ W1,
        const float* __restrict__ query, const float* __restrict__ vhq,
        const float* __restrict__ vcq) {
    __shared__ float shbuf[1088];
    int bid = blockIdx.x;
    int tid = threadIdx.x;

    if (bid < 384) {
        int b = bid / 24, cht = bid % 24;
        int c = tid & 63, sl = tid >> 6;
        int ch = cht * 64 + c;
        float s = 0.f, s2 = 0.f;
        const float* p = ht + (size_t)b * TT * CC + ch;
        for (int t = sl; t < TT; t += 4) {
            float v = p[(size_t)t * CC];
            s += v; s2 += v * v;
        }
        shbuf[sl * 64 + c] = s;
        shbuf[256 + sl * 64 + c] = s2;
        __syncthreads();
        if (sl == 0) {
            for (int j = 1; j < 4; j++) { s += shbuf[j * 64 + c]; s2 += shbuf[256 + j * 64 + c]; }
            float mean = s * (1.f / TT);
            float var = (s2 - (float)TT * mean * mean) * (1.f / (TT - 1));
            float sd = sqrtf(fmaxf(var, 0.f));
            g_c[((size_t)b * CC + ch) * 2 + 0] = mean;
            g_c[((size_t)b * CC + ch) * 2 + 1] = sd;
        }
    } else if (bid < 768) {
        int idx = bid - 384;
        int tile = idx % 48, n = idx / 48;
        int d0 = (tile % 6) * 32, q0 = (tile / 6) * 32;
        int tx = tid & 31, ty = tid >> 5;
#pragma unroll
        for (int j = 0; j < 4; j++)
            shbuf[(ty + j * 8) * 33 + tx] = W1[((size_t)n * DD + d0 + ty + j * 8) * QQ + q0 + tx];
        __syncthreads();
#pragma unroll
        for (int j = 0; j < 4; j++)
            g_w1t[((size_t)n * QQ + q0 + ty + j * 8) * DD + d0 + tx] =
                __float2bfloat16_rn(shbuf[tx * 33 + ty + j * 8]);
    } else if (bid < 1152) {
        int idx = bid - 768;
        int tile = idx % 48, n = idx / 48;
        int a0 = (tile % 6) * 32, q0 = (tile / 6) * 32;
        int tx = tid & 31, ty = tid >> 5;
#pragma unroll
        for (int j = 0; j < 4; j++)
            shbuf[(ty + j * 8) * 33 + tx] = query[((size_t)n * QQ + q0 + ty + j * 8) * AA + a0 + tx];
        __syncthreads();
#pragma unroll
        for (int j = 0; j < 4; j++)
            g_qTb[((size_t)n * AA + a0 + ty + j * 8) * QQ + q0 + tx] =
                __float2bfloat16_rn(shbuf[tx * 33 + ty + j * 8] * (1.f / 16.f));
    } else {
        int idx = bid - 1152;
        int s = idx % 8, n = idx / 8;
        float acc = 0.f;
        int base = s * (AA * QQ / 8);
        for (int ii = tid; ii < AA * QQ / 8; ii += 256) {
            int i = base + ii;
            int a = i >> 8, q = i & 255;
            acc += query[(n * QQ + q) * AA + a] * vhq[n * AA * QQ + i];
        }
        shbuf[tid] = acc;
        __syncthreads();
        for (int off = 128; off > 0; off >>= 1) {
            if (tid < off) shbuf[tid] += shbuf[tid + off];
            __syncthreads();
        }
        if (tid == 0) g_qdotp[n * 8 + s] = shbuf[0];

        int w = tid >> 5, lane = tid & 31;
        for (int r = w; r < AA / 8; r += 8) {
            int a = s * (AA / 8) + r;
            const float* vp = vcq + ((size_t)n * AA + a) * QQ;
            float sum = 0.f;
            for (int q = lane; q < QQ; q += 32) sum += vp[q];
#pragma unroll
            for (int o = 16; o > 0; o >>= 1) sum += __shfl_down_sync(0xffffffffu, sum, o);
            if (lane == 0) g_vcqsum[n * AA + a] = sum;
        }
    }
}

// ---------------- ctx-a: hck + t1 + ckdot partials -------------------------
__global__ __launch_bounds__(256) void k_ctx_a(
        const float* __restrict__ uk_W, const float* __restrict__ u_q1W,
        const float* __restrict__ u_q1b, const float* __restrict__ vck,
        const float* __restrict__ bnc_g, const float* __restrict__ bnc_b,
        const float* __restrict__ bnc_m, const float* __restrict__ bnc_v) {
    int n = blockIdx.y, qt = blockIdx.x;
    int tid = threadIdx.x;
    int qi = tid & 31, sl = tid >> 5;
    int q = qt * 32 + qi;

    __shared__ float c_sh[16 * 384];
    __shared__ float part[8 * 16 * 33];

    for (int i = tid; i < 16 * 384; i += 256) {
        int b = i / 384, l = i - b * 384;
        c_sh[i] = g_c[((size_t)b * CC + n * DD) * 2 + l];
    }
    __syncthreads();

    float ak[16], aq[16];
#pragma unroll
    for (int b = 0; b < 16; b++) { ak[b] = 0.f; aq[b] = 0.f; }
    {
        const float* uk = uk_W + ((size_t)n * 384) * QQ + q;
        const float* u1 = u_q1W + ((size_t)n * 384) * QQ + q;
        int l0 = sl * 48;
        for (int l = l0; l < l0 + 48; l++) {
            float wk = uk[(size_t)l * QQ];
            float w1 = u1[(size_t)l * QQ];
            const float* cb = c_sh + l;
#pragma unroll
            for (int b = 0; b < 16; b++) {
                float cv = cb[b * 384];
                ak[b] = fmaf(cv, wk, ak[b]);
                aq[b] = fmaf(cv, w1, aq[b]);
            }
        }
    }

#pragma unroll
    for (int b = 0; b < 16; b++) part[(sl * 16 + b) * 33 + qi] = ak[b];
    __syncthreads();
    {
        int bp = tid >> 5;
        float s0 = 0.f, s1 = 0.f;
#pragma unroll
        for (int s = 0; s < 8; s++) {
            s0 += part[(s * 16 + bp) * 33 + qi];
            s1 += part[(s * 16 + bp + 8) * 33 + qi];
        }
        g_hck[((size_t)(bp * NH + n)) * QQ + q] = s0;
        g_hck[((size_t)((bp + 8) * NH + n)) * QQ + q] = s1;

        float vckq = vck[n * QQ + q];
        float p0 = s0 * vckq, p1 = s1 * vckq;
#pragma unroll
        for (int o = 16; o > 0; o >>= 1) {
            p0 += __shfl_down_sync(0xffffffffu, p0, o);
            p1 += __shfl_down_sync(0xffffffffu, p1, o);
        }
        if (qi == 0) {
            g_ckdotp[(bp * NH + n) * 8 + qt] = p0;
            g_ckdotp[((bp + 8) * NH + n) * 8 + qt] = p1;
        }
    }
    __syncthreads();

#pragma unroll
    for (int b = 0; b < 16; b++) part[(sl * 16 + b) * 33 + qi] = aq[b];
    __syncthreads();
    {
        int bp = tid >> 5;
        float s0 = 0.f, s1 = 0.f;
#pragma unroll
        for (int s = 0; s < 8; s++) {
            s0 += part[(s * 16 + bp) * 33 + qi];
            s1 += part[(s * 16 + bp + 8) * 33 + qi];
        }
        float bias = u_q1b[n * QQ + q];
        float grs = bnc_g[q] * rsqrtf(bnc_v[q] + 1e-5f);
        float beta = bnc_b[q] - grs * bnc_m[q];
        float r0 = fmaxf(s0 + bias, 0.f);
        float r1 = fmaxf(s1 + bias, 0.f);
        g_t1[((size_t)(bp * NH + n)) * QQ + q] = tanhf(fmaf(grs, r0, beta));
        g_t1[((size_t)((bp + 8) * NH + n)) * QQ + q] = tanhf(fmaf(grs, r1, beta));
    }
}

// ---------------- ctx-b: cq2 + vcqdot partials ------------------------------
__global__ __launch_bounds__(256) void k_ctx_b(const float* __restrict__ u_q2) {
    int n = blockIdx.y, at = blockIdx.x;
    int tid = threadIdx.x;
    int ai = tid & 31, msl = tid >> 5;
    int a = at * 32 + ai;

    __shared__ float t1_sh[16 * 256];
    __shared__ float part[8 * 16 * 33];

    for (int i = tid; i < 16 * 256; i += 256) {
        int b = i >> 8, m = i & 255;
        t1_sh[i] = g_t1[((size_t)(b * NH + n)) * QQ + m];
    }
    __syncthreads();

    float acc[16];
#pragma unroll
    for (int b = 0; b < 16; b++) acc[b] = 0.f;
    {
        const float* u2 = u_q2 + (size_t)n * QQ * AA + a;
        int m0 = msl * 32;
        for (int m = m0; m < m0 + 32; m++) {
            float w = u2[(size_t)m * AA];
            const float* tb = t1_sh + m;
#pragma unroll
            for (int b = 0; b < 16; b++)
                acc[b] = fmaf(tb[b * 256], w, acc[b]);
        }
    }
#pragma unroll
    for (int b = 0; b < 16; b++) part[(msl * 16 + b) * 33 + ai] = acc[b];
    __syncthreads();
    {
        int bp = tid >> 5;
        float s0 = 0.f, s1 = 0.f;
#pragma unroll
        for (int s = 0; s < 8; s++) {
            s0 += part[(s * 16 + bp) * 33 + ai];
            s1 += part[(s * 16 + bp + 8) * 33 + ai];
        }
        g_cq2[((size_t)(bp * NH + n)) * AA + a] = s0;
        g_cq2[((size_t)((bp + 8) * NH + n)) * AA + a] = s1;

        float vs = g_vcqsum[n * AA + a];
        float p0 = s0 * vs, p1 = s1 * vs;
#pragma unroll
        for (int o = 16; o > 0; o >>= 1) {
            p0 += __shfl_down_sync(0xffffffffu, p0, o);
            p1 += __shfl_down_sync(0xffffffffu, p1, o);
        }
        if (ai == 0) {
            g_vcqdotp[(bp * NH + n) * 6 + at] = p0;
            g_vcqdotp[((bp + 8) * NH + n) * 6 + at] = p1;
        }
    }
}

// ---------------- K3: fused scores + pool (M=64, 2 CTAs/SM) ----------------
// smem:
//  SM_HK  [0, 33792):         k2 bf16 [64][264]
//  SM_XS  [33792, 59392):     x tile bf16 [64][200]; qT rows / dump0
//  W1 A/B [59392, 84992):     2x 12.8K; qT tail / dump1
//  SM_AUX [84992, ...)
#define XS_STRIDE 200
#define HK_STRIDE 264
#define SS_STRIDE 100
#define SM_HK 0
#define SM_XS 33792
#define SM_W1A 59392
#define SM_W1B 72192
#define SM_AUX 84992
#define AXH_HCK  (SM_AUX + 0)
#define AXH_KBV  (SM_AUX + 1024)
#define AXH_GRS  (SM_AUX + 2048)
#define AXH_BETA (SM_AUX + 3072)
#define AXH_VHK  (SM_AUX + 4096)
#define AXH_QB   (SM_AUX + 5120)
#define AXH_CQ2  (SM_AUX + 5888)
#define AXH_RS   (SM_AUX + 6656)   // 4 x 64 rowsum partials
#define AXH_LAMP (SM_AUX + 7680)   // 2 x 64 lambda partials
#define AXH_LAM  (SM_AUX + 8192)   // 64 finals
#define AXH_SCAL (SM_AUX + 8448)
#define SMEM_SC  (SM_AUX + 8464)

__global__ __launch_bounds__(256, 2) void k_scores_mma(
        const float* __restrict__ ht, const float* __restrict__ kb,
        const float* __restrict__ bg, const float* __restrict__ bbias,
        const float* __restrict__ bm, const float* __restrict__ bv,
        const float* __restrict__ vhk, const float* __restrict__ qb) {
    extern __shared__ char smem[];
    uint32_t sb = smem_u32(smem);
    int tid = threadIdx.x;
    int w = tid >> 5, lane = tid & 31;
    int rg = w & 3, sub = w >> 2;
    int bn = blockIdx.y;
    int b = bn >> 3, n = bn & 7;
    int tile = blockIdx.x;
    int t0 = tile * 64;

    // W1 chunk 0 (32 q x 192 d) async
    {
        const uint4* wsrc = (const uint4*)(g_w1t + (size_t)n * QQ * DD);
#pragma unroll
        for (int it = 0; it < 3; it++) {
            int idx = it * 256 + tid;
            int row = idx / 24, c8 = idx - row * 24;
            CP_ASYNC16(sb + SM_W1A + (row * XS_STRIDE + c8 * 8) * 2, wsrc + idx);
        }
        CP_COMMIT();
    }

    // aux constants + per-bn scalars
    {
        int i = tid;
        float g = bg[i];
        float grs = g * rsqrtf(bv[i] + 1e-5f);
        ((float*)(smem + AXH_GRS))[i] = grs;
        ((float*)(smem + AXH_BETA))[i] = bbias[i] - grs * bm[i];
        ((float*)(smem + AXH_HCK))[i] = g_hck[(size_t)bn * QQ + i];
        ((float*)(smem + AXH_KBV))[i] = kb[n * QQ + i];
        ((float*)(smem + AXH_VHK))[i] = vhk[n * QQ + i];
        if (i < AA) {
            ((float*)(smem + AXH_QB))[i] = qb[n * AA + i];
            ((float*)(smem + AXH_CQ2))[i] = g_cq2[(size_t)bn * AA + i];
        }
        if (i == 0) {
            float qd = 0.f;
#pragma unroll
            for (int k = 0; k < 8; k++) qd += g_qdotp[n * 8 + k];
            float vq = 0.f;
#pragma unroll
            for (int k = 0; k < 6; k++) vq += g_vcqdotp[bn * 6 + k];
            ((float*)(smem + AXH_SCAL))[0] = 1.f / (1.f + __expf(-(qd + vq)));
            float ck = 0.f;
#pragma unroll
            for (int k = 0; k < 8; k++) ck += g_ckdotp[bn * 8 + k];
            ((float*)(smem + AXH_SCAL))[1] = ck;
        }
    }

    // ---- x tile (64 x 192 fp32 -> bf16), zero-pad past TT ----
    {
        const float* xb = ht + ((size_t)b * TT + t0) * CC + n * DD;
#pragma unroll
        for (int it = 0; it < 12; it++) {
            int idx = it * 256 + tid;
            int row = idx / 48, c4 = idx - row * 48;
            float4 v = make_float4(0.f, 0.f, 0.f, 0.f);
            if (t0 + row < TT) v = *(const float4*)(xb + (size_t)row * CC + c4 * 4);
            uint2 pk = make_uint2(pack_bf(v.x, v.y), pack_bf(v.z, v.w));
            *(uint2*)(smem + SM_XS + (row * XS_STRIDE + c4 * 4) * 2) = pk;
        }
    }
    __syncthreads();

    // hoist A-fragments (rows rg*16..+15, K=192)
    uint32_t afr[12][4];
    {
        uint32_t abase = sb + SM_XS + ((rg * 16 + (lane & 15)) * XS_STRIDE + (lane >> 4) * 8) * 2;
#pragma unroll
        for (int kk = 0; kk < 12; kk++) ldsm_x4(afr[kk], abase + kk * 32);
    }

    uint32_t boff_w1 = ((sub * 16 + (lane >> 4) * 8 + (lane & 7)) * XS_STRIDE
                        + ((lane >> 3) & 1) * 8) * 2;
    int r0 = rg * 16 + (lane >> 2);

    // ---- GEMM1: 8 q-chunks of 32, double-buffered W1 ----
    float lam0 = 0.f, lam1 = 0.f;
    for (int qc = 0; qc < 8; qc++) {
        if (qc < 7) {
            int buf = ((qc + 1) & 1) ? SM_W1B : SM_W1A;
            const uint4* wsrc = (const uint4*)(g_w1t + ((size_t)n * QQ + (qc + 1) * 32) * DD);
#pragma unroll
            for (int it = 0; it < 3; it++) {
                int idx = it * 256 + tid;
                int row = idx / 24, c8 = idx - row * 24;
                CP_ASYNC16(sb + buf + (row * XS_STRIDE + c8 * 8) * 2, wsrc + idx);
            }
            CP_COMMIT();
            CP_WAIT1();
        } else {
            CP_WAIT0();
        }
        __syncthreads();

        uint32_t bbase = sb + ((qc & 1) ? SM_W1B : SM_W1A) + boff_w1;

        float c[2][4];
#pragma unroll
        for (int j = 0; j < 2; j++)
#pragma unroll
            for (int e = 0; e < 4; e++) c[j][e] = 0.f;

#pragma unroll
        for (int kk = 0; kk < 12; kk++) {
            uint32_t bf[4];
            ldsm_x4(bf, bbase + kk * 32);
            mma_bf16(c[0], afr[kk], bf[0], bf[1]);
            mma_bf16(c[1], afr[kk], bf[2], bf[3]);
        }

        const float* vhk_s = (const float*)(smem + AXH_VHK);
#pragma unroll
        for (int j = 0; j < 2; j++) {
            int col = qc * 32 + sub * 16 + j * 8 + 2 * (lane & 3);
            float v0 = vhk_s[col], v1 = vhk_s[col + 1];
            lam0 += c[j][0] * v0 + c[j][1] * v1;
            lam1 += c[j][2] * v0 + c[j][3] * v1;
            *(uint32_t*)(smem + SM_HK + (r0 * HK_STRIDE + col) * 2) =
                pack_bf(c[j][0], c[j][1]);
            *(uint32_t*)(smem + SM_HK + ((r0 + 8) * HK_STRIDE + col) * 2) =
                pack_bf(c[j][2], c[j][3]);
        }
        __syncthreads();   // buffer reads done before re-fill
    }

    // prefetch qT chunk 0 (96 rows x 256 q) into contiguous XS+W1 region
    {
        const uint4* hs = (const uint4*)(g_qTb + (size_t)n * AA * QQ);
#pragma unroll
        for (int it = 0; it < 12; it++) {
            int idx = it * 256 + tid;
            int row = idx / 32, c8 = idx - row * 32;
            CP_ASYNC16(sb + SM_XS + (row * HK_STRIDE + c8 * 8) * 2, hs + idx);
        }
        CP_COMMIT();
    }

    // lambda finalize
    lam0 += __shfl_xor_sync(0xffffffffu, lam0, 1);
    lam0 += __shfl_xor_sync(0xffffffffu, lam0, 2);
    lam1 += __shfl_xor_sync(0xffffffffu, lam1, 1);
    lam1 += __shfl_xor_sync(0xffffffffu, lam1, 2);
    if ((lane & 3) == 0) {
        float* lp = (float*)(smem + AXH_LAMP);
        lp[sub * 64 + r0] = lam0;
        lp[sub * 64 + r0 + 8] = lam1;
    }
    __syncthreads();
    if (tid < 64) {
        const float* lp = (const float*)(smem + AXH_LAMP);
        float ckd = ((const float*)(smem + AXH_SCAL))[1];
        float s = lp[tid] + lp[64 + tid] + ckd;
        ((float*)(smem + AXH_LAM))[tid] = 1.f / (1.f + __expf(-s));
    }
    __syncthreads();

    // ---- activation in place on HK + rowsums ----
    {
        int row = tid >> 2;
        int cb = (tid & 3) * 64;
        float lam = ((const float*)(smem + AXH_LAM))[row];
        const float* hck_s = (const float*)(smem + AXH_HCK);
        const float* kbv_s = (const float*)(smem + AXH_KBV);
        const float* grs_s = (const float*)(smem + AXH_GRS);
        const float* bet_s = (const float*)(smem + AXH_BETA);
        uint32_t* hp = (uint32_t*)(smem + SM_HK + (row * HK_STRIDE + cb) * 2);
        float rs_acc = 0.f;
#pragma unroll
        for (int j = 0; j < 8; j++) {
            uint4 v = *(uint4*)(hp + j * 4);
            uint32_t* vr = (uint32_t*)&v;
#pragma unroll
            for (int e = 0; e < 4; e++) {
                int c0 = cb + j * 8 + 2 * e;
                float h0 = bflo(vr[e]), h1 = bfhi(vr[e]);
                float m0 = fmaf(lam, hck_s[c0] - h0, h0) + kbv_s[c0];
                float m1 = fmaf(lam, hck_s[c0 + 1] - h1, h1) + kbv_s[c0 + 1];
                m0 = fmaxf(m0, 0.f); m1 = fmaxf(m1, 0.f);
                float a0 = tanha(fmaf(grs_s[c0], m0, bet_s[c0]));
                float a1 = tanha(fmaf(grs_s[c0 + 1], m1, bet_s[c0 + 1]));
                rs_acc += a0 + a1;
                vr[e] = pack_bf(a0, a1);
            }
            *(uint4*)(hp + j * 4) = v;
        }
        ((float*)(smem + AXH_RS))[(tid & 3) * 64 + row] = rs_acc;
    }
    CP_WAIT0();   // qT chunk 0 resident
    __syncthreads();

    // ---- GEMM2: 2 a-chunks of 96 vs qT; both acc sets in registers ----
    uint32_t abase2 = sb + SM_HK + ((rg * 16 + (lane & 15)) * HK_STRIDE + (lane >> 4) * 8) * 2;
    uint32_t boff_q = ((sub * 48 + (lane >> 4) * 8 + (lane & 7)) * HK_STRIDE
                       + ((lane >> 3) & 1) * 8) * 2;

    float c2a[3][2][4], c2b[3][2][4];
#pragma unroll
    for (int p = 0; p < 3; p++)
#pragma unroll
        for (int j = 0; j < 2; j++)
#pragma unroll
            for (int e = 0; e < 4; e++) { c2a[p][j][e] = 0.f; c2b[p][j][e] = 0.f; }

#pragma unroll 4
    for (int kk = 0; kk < 16; kk++) {
        uint32_t a[4];
        ldsm_x4(a, abase2 + kk * 32);
#pragma unroll
        for (int p = 0; p < 3; p++) {
            uint32_t bf[4];
            ldsm_x4(bf, sb + SM_XS + boff_q + p * 16 * HK_STRIDE * 2 + kk * 32);
            mma_bf16(c2a[p][0], a, bf[0], bf[1]);
            mma_bf16(c2a[p][1], a, bf[2], bf[3]);
        }
    }
    __syncthreads();   // chunk-0 qT reads done

    // load qT chunk 1 (a 96..191)
    {
        const uint4* hs = (const uint4*)(g_qTb + ((size_t)n * AA + 96) * QQ);
#pragma unroll
        for (int it = 0; it < 12; it++) {
            int idx = it * 256 + tid;
            int row = idx / 32, c8 = idx - row * 32;
            CP_ASYNC16(sb + SM_XS + (row * HK_STRIDE + c8 * 8) * 2, hs + idx);
        }
        CP_COMMIT();
        CP_WAIT0();
    }
    __syncthreads();

#pragma unroll 4
    for (int kk = 0; kk < 16; kk++) {
        uint32_t a[4];
        ldsm_x4(a, abase2 + kk * 32);
#pragma unroll
        for (int p = 0; p < 3; p++) {
            uint32_t bf[4];
            ldsm_x4(bf, sb + SM_XS + boff_q + p * 16 * HK_STRIDE * 2 + kk * 32);
            mma_bf16(c2b[p][0], a, bf[0], bf[1]);
            mma_bf16(c2b[p][1], a, bf[2], bf[3]);
        }
    }
    __syncthreads();   // qT region + HK fully dead

    // dump with rank-1 + (1-lamq) scaling: chunk0 -> XS, chunk1 -> W1A
    {
        float lamq = ((const float*)(smem + AXH_SCAL))[0];
        float onem = 1.f - lamq;
        float lqs = lamq * (1.f / 16.f);
        const float* rsp = (const float*)(smem + AXH_RS);
        const float* cq2_s = (const float*)(smem + AXH_CQ2);
        float rsa = (rsp[r0] + rsp[64 + r0] + rsp[128 + r0] + rsp[192 + r0]) * lqs;
        float rsb = (rsp[r0 + 8] + rsp[64 + r0 + 8] + rsp[128 + r0 + 8] + rsp[192 + r0 + 8]) * lqs;
        float* d0 = (float*)(smem + SM_XS);
        float* d1 = (float*)(smem + SM_W1A);
#pragma unroll
        for (int p = 0; p < 3; p++) {
#pragma unroll
            for (int j = 0; j < 2; j++) {
                int col = sub * 48 + p * 16 + j * 8 + 2 * (lane & 3);
                float cqa0 = cq2_s[col], cqb0 = cq2_s[col + 1];
                float cqa1 = cq2_s[96 + col], cqb1 = cq2_s[96 + col + 1];
                *(float2*)(d0 + r0 * SS_STRIDE + col) = make_float2(
                    fmaf(onem, c2a[p][j][0], rsa * cqa0),
                    fmaf(onem, c2a[p][j][1], rsa * cqb0));
                *(float2*)(d0 + (r0 + 8) * SS_STRIDE + col) = make_float2(
                    fmaf(onem, c2a[p][j][2], rsb * cqa0),
                    fmaf(onem, c2a[p][j][3], rsb * cqb0));
                *(float2*)(d1 + r0 * SS_STRIDE + col) = make_float2(
                    fmaf(onem, c2b[p][j][0], rsa * cqa1),
                    fmaf(onem, c2b[p][j][1], rsa * cqb1));
                *(float2*)(d1 + (r0 + 8) * SS_STRIDE + col) = make_float2(
                    fmaf(onem, c2b[p][j][2], rsb * cqa1),
                    fmaf(onem, c2b[p][j][3], rsb * cqb1));
            }
        }
    }
    __syncthreads();

    // ---- fused softmax partials: thread == a (192 active) -----------------
    if (tid < AA) {
        int a = tid;
        const float* ssm = (a < 96) ? (const float*)(smem + SM_XS)
                                    : (const float*)(smem + SM_W1A);
        int acol = (a < 96) ? a : (a - 96);
        float qbv = ((const float*)(smem + AXH_QB))[a];
        int tmax = TT - t0; if (tmax > 64) tmax = 64;

        float M = -1e30f;
        for (int t = 0; t < 64; t++)            // padded rows bounded; exact shift
            M = fmaxf(M, ssm[t * SS_STRIDE + acol]);
        M += qbv;

        float Z = 0.f, S1 = 0.f, S2 = 0.f;
        const float* vp = ht + ((size_t)b * TT + t0) * CC + n * DD + a;
#pragma unroll 4
        for (int t = 0; t < tmax; t++) {
            float s = ssm[t * SS_STRIDE + acol] + qbv;
            float wv = __expf(s - M);
            float v = vp[(size_t)t * CC];
            Z += wv; S1 += wv * v; S2 += wv * v * v;
        }
        g_pp[((size_t)bn * 32 + tile) * AA + a] = make_float4(M, Z, S1, S2);
    }
}

// ---------------- K4: merge 32 tile partials -> output ---------------------
__global__ __launch_bounds__(192) void k_pool_merge(float* __restrict__ out) {
    int bn = blockIdx.x;
    int b = bn >> 3, n = bn & 7;
    int a = threadIdx.x;

    const float4* pp = g_pp + (size_t)bn * 32 * AA + a;
    float M = -1e30f;
#pragma unroll
    for (int s = 0; s < 32; s++) M = fmaxf(M, pp[s * AA].x);
    float Zt = 0.f, S1t = 0.f, S2t = 0.f;
#pragma unroll
    for (int s = 0; s < 32; s++) {
        float4 p = pp[s * AA];
        float c = __expf(p.x - M);
        Zt += p.y * c; S1t += p.z * c; S2t += p.w * c;
    }
    float mu = S1t / Zt;
    float ex2 = S2t / Zt;
    float rh = sqrtf(fmaxf(ex2 - mu * mu, 1e-9f));
    out[(size_t)b * (2 * CC) + n * DD + a] = mu;
    out[(size_t)b * (2 * CC) + CC + n * DD + a] = rh;
}

// ---------------- launcher ------------------------------------------------
extern "C" void kernel_launch(void* const* d_in, const int* in_sizes, int n_in,
                              void* d_out, int out_size) {
    const float* ht       = (const float*)d_in[0];
    const float* k_proj_W = (const float*)d_in[1];
    const float* query    = (const float*)d_in[2];
    const float* uk_W     = (const float*)d_in[3];
    const float* u_q1W    = (const float*)d_in[4];
    const float* u_q2     = (const float*)d_in[5];
    const float* vhq      = (const float*)d_in[6];
    const float* vhk      = (const float*)d_in[7];
    const float* vcq      = (const float*)d_in[8];
    const float* vck      = (const float*)d_in[9];
    const float* k_proj_b = (const float*)d_in[10];
    const float* q_b      = (const float*)d_in[11];
    const float* u_q1b    = (const float*)d_in[12];
    const float* bnc_g    = (const float*)d_in[13];
    const float* bnc_b    = (const float*)d_in[14];
    const float* bnc_m    = (const float*)d_in[15];
    const float* bnc_v    = (const float*)d_in[16];
    const float* bnk_g    = (const float*)d_in[17];
    const float* bnk_b    = (const float*)d_in[18];
    const float* bnk_m    = (const float*)d_in[19];
    const float* bnk_v    = (const float*)d_in[20];
    float* out = (float*)d_out;

    static int smem_set = 0;
    if (!smem_set) {
        cudaFuncSetAttribute(k_scores_mma,
                             cudaFuncAttributeMaxDynamicSharedMemorySize, SMEM_SC);
        smem_set = 1;
    }

    // launch 1: fused front
    k_front<<<1216, 256>>>(ht, k_proj_W, query, vhq, vcq);

    // launch 2: ctx_a
    dim3 ga(8, NH);
    k_ctx_a<<<ga, 256>>>(uk_W, u_q1W, u_q1b, vck, bnc_g, bnc_b, bnc_m, bnc_v);

    // launch 3: ctx_b
    dim3 gb(6, NH);
    k_ctx_b<<<gb, 256>>>(u_q2);

    // launch 4 (ncu-captured): full-grid fused scores kernel (M=64, 2 CTA/SM)
    dim3 gsc(32, BB * NH);
    k_scores_mma<<<gsc, 256, SMEM_SC>>>(ht, k_proj_b, bnk_g, bnk_b, bnk_m, bnk_v,
                                        vhk, q_b);

    // launch 5: merge
    k_pool_merge<<<BB * NH, AA>>>(out);
}